// round 2
// baseline (speedup 1.0000x reference)
#include <cuda_runtime.h>

// out[n, i] = b[n, i] * sum_j a[n, j]
// B = L = 8192, fp32. One WARP per row: no block barriers, single resident wave.

constexpr int L = 8192;
constexpr int THREADS = 256;
constexpr int WARPS_PER_BLOCK = THREADS / 32;          // 8 rows per block
constexpr int VECS_PER_ROW = L / 4;                    // 2048 float4 per row
constexpr int VECS_PER_LANE = VECS_PER_ROW / 32;       // 64 float4 per lane
constexpr int UNROLL = 8;                              // 8 outstanding LDG.128

__global__ __launch_bounds__(THREADS)
void outer_product_rowscale(const float* __restrict__ a,
                            const float* __restrict__ b,
                            float* __restrict__ out)
{
    const int warp = threadIdx.x >> 5;
    const int lane = threadIdx.x & 31;
    const int row  = blockIdx.x * WARPS_PER_BLOCK + warp;

    const float4* a4 = reinterpret_cast<const float4*>(a) + (size_t)row * VECS_PER_ROW;
    const float4* b4 = reinterpret_cast<const float4*>(b) + (size_t)row * VECS_PER_ROW;
    float4* o4       = reinterpret_cast<float4*>(out)     + (size_t)row * VECS_PER_ROW;

    // ---- Phase 1: row-sum of a. 64 float4/lane in batches of 8 (MLP=8). ----
    float s0 = 0.0f, s1 = 0.0f, s2 = 0.0f, s3 = 0.0f;
    #pragma unroll
    for (int base = 0; base < VECS_PER_LANE; base += UNROLL) {
        float4 v[UNROLL];
        #pragma unroll
        for (int i = 0; i < UNROLL; i++)
            v[i] = __ldcs(&a4[lane + (base + i) * 32]);
        #pragma unroll
        for (int i = 0; i < UNROLL; i++) {
            s0 += v[i].x; s1 += v[i].y; s2 += v[i].z; s3 += v[i].w;
        }
    }
    float s = (s0 + s1) + (s2 + s3);

    // warp-only reduce + broadcast (no __syncthreads anywhere)
    #pragma unroll
    for (int off = 16; off > 0; off >>= 1)
        s += __shfl_xor_sync(0xFFFFFFFFu, s, off);
    const float scale = s;   // xor-shuffle leaves full sum in every lane

    // ---- Phase 2: out = b * scale, streaming, batches of 8 ----
    #pragma unroll
    for (int base = 0; base < VECS_PER_LANE; base += UNROLL) {
        float4 v[UNROLL];
        #pragma unroll
        for (int i = 0; i < UNROLL; i++)
            v[i] = __ldcs(&b4[lane + (base + i) * 32]);
        #pragma unroll
        for (int i = 0; i < UNROLL; i++) {
            v[i].x *= scale; v[i].y *= scale; v[i].z *= scale; v[i].w *= scale;
            __stcs(&o4[lane + (base + i) * 32], v[i]);
        }
    }
}

extern "C" void kernel_launch(void* const* d_in, const int* in_sizes, int n_in,
                              void* d_out, int out_size)
{
    const float* a = (const float*)d_in[0];
    const float* b = (const float*)d_in[1];
    float* out = (float*)d_out;

    const int rows = in_sizes[0] / L;                  // 8192
    outer_product_rowscale<<<rows / WARPS_PER_BLOCK, THREADS>>>(a, b, out);
}

// round 3
// speedup vs baseline: 1.0365x; 1.0365x over previous
#include <cuda_runtime.h>
#include <cuda_pipeline.h>

// out[n, i] = b[n, i] * sum_j a[n, j]
// B = L = 8192, fp32. One CTA per row.
// b is staged SMEM via cp.async CONCURRENTLY with the a-reduction reads, so each
// CTA's full 64KB of DRAM reads issue in one dense burst; after the reduction
// barrier only stores remain.

constexpr int L = 8192;
constexpr int THREADS = 256;
constexpr int VECS_PER_ROW = L / 4;                      // 2048 float4
constexpr int VPT = VECS_PER_ROW / THREADS;              // 8 per thread

__global__ __launch_bounds__(THREADS)
void outer_product_rowscale(const float* __restrict__ a,
                            const float* __restrict__ b,
                            float* __restrict__ out)
{
    __shared__ float4 sb[VECS_PER_ROW];                  // 32 KB: b row staging
    __shared__ float warp_sums[THREADS / 32];
    __shared__ float row_sum;

    const int row = blockIdx.x;
    const int tid = threadIdx.x;

    const float4* a4 = reinterpret_cast<const float4*>(a) + (size_t)row * VECS_PER_ROW;
    const float4* b4 = reinterpret_cast<const float4*>(b) + (size_t)row * VECS_PER_ROW;
    float4* o4       = reinterpret_cast<float4*>(out)     + (size_t)row * VECS_PER_ROW;

    // ---- Issue b -> smem copies first (async, L1-bypassing, no registers) ----
    #pragma unroll
    for (int i = 0; i < VPT; i++)
        __pipeline_memcpy_async(&sb[tid + i * THREADS], &b4[tid + i * THREADS],
                                sizeof(float4));
    __pipeline_commit();

    // ---- Concurrently: row-sum of a (coalesced, streaming) ----
    float s0 = 0.f, s1 = 0.f, s2 = 0.f, s3 = 0.f;
    #pragma unroll
    for (int i = 0; i < VPT; i++) {
        float4 v = __ldcs(&a4[tid + i * THREADS]);
        s0 += v.x; s1 += v.y; s2 += v.z; s3 += v.w;
    }
    float s = (s0 + s1) + (s2 + s3);

    #pragma unroll
    for (int off = 16; off > 0; off >>= 1)
        s += __shfl_xor_sync(0xFFFFFFFFu, s, off);

    if ((tid & 31) == 0) warp_sums[tid >> 5] = s;
    __syncthreads();
    if (tid == 0) {
        float t = 0.f;
        #pragma unroll
        for (int w = 0; w < THREADS / 32; w++) t += warp_sums[w];
        row_sum = t;
    }

    // Wait for b staging + reduction result, then pure store phase.
    __pipeline_wait_prior(0);
    __syncthreads();

    const float scale = row_sum;

    #pragma unroll
    for (int i = 0; i < VPT; i++) {
        float4 v = sb[tid + i * THREADS];
        v.x *= scale; v.y *= scale; v.z *= scale; v.w *= scale;
        __stcs(&o4[tid + i * THREADS], v);
    }
}

extern "C" void kernel_launch(void* const* d_in, const int* in_sizes, int n_in,
                              void* d_out, int out_size)
{
    const float* a = (const float*)d_in[0];
    const float* b = (const float*)d_in[1];
    float* out = (float*)d_out;

    const int rows = in_sizes[0] / L;                    // 8192
    outer_product_rowscale<<<rows, THREADS>>>(a, b, out);
}